// round 6
// baseline (speedup 1.0000x reference)
#include <cuda_runtime.h>
#include <cuda_bf16.h>

#define BDIM 256
#define NROWS 4096
#define DCOLS 8192
#define ROWS_PER_BLOCK 2
#define NBLOCKS (NROWS / ROWS_PER_BLOCK)   // 2048

__device__ float g_partials[NBLOCKS];
__device__ unsigned int g_done_count;      // zero-init; self-resetting

__device__ __forceinline__ float smoothl1(float a, float b) {
    float d = a - b;
    float ad = fabsf(d);
    return (ad < 1.0f) ? (0.5f * d * d) : (ad - 0.5f);
}

// Per-thread partial over one row: two 4-pair front-batched halves.
// With the (256,4) launch bounds there is register room for the full
// 8 x LDG.128 batch (32 data regs) to stay live.
__device__ __forceinline__ float row_partial(const float* __restrict__ in,
                                             const float* __restrict__ tgt,
                                             int row, int tid) {
    const float4* __restrict__ A =
        reinterpret_cast<const float4*>(in  + (size_t)row * DCOLS);
    const float4* __restrict__ B =
        reinterpret_cast<const float4*>(tgt + (size_t)row * DCOLS);

    float acc0 = 0.0f, acc1 = 0.0f;
    #pragma unroll
    for (int half = 0; half < 2; ++half) {
        float4 x[4], y[4];
        #pragma unroll
        for (int j = 0; j < 4; ++j) {
            int i = (half * 4 + j) * BDIM + tid;
            x[j] = A[i];
            y[j] = B[i];
        }
        #pragma unroll
        for (int j = 0; j < 4; ++j) {
            acc0 += smoothl1(x[j].x, y[j].x);
            acc1 += smoothl1(x[j].y, y[j].y);
            acc0 += smoothl1(x[j].z, y[j].z);
            acc1 += smoothl1(x[j].w, y[j].w);
        }
    }
    return acc0 + acc1;
}

__global__ __launch_bounds__(BDIM, 4)   // cap 4 CTAs/SM -> up to 64 regs/thread
void mask_smoothl1_fused_kernel(const float* __restrict__ in,
                                const float* __restrict__ tgt,
                                const int* __restrict__ mask,
                                float* __restrict__ out) {
    const int bid = blockIdx.x;
    const int tid = threadIdx.x;

    const int2 mm = reinterpret_cast<const int2*>(mask)[bid];
    const int r0 = bid * 2;

    float acc = 0.0f;
    if (mm.x != 0) acc += (float)mm.x * row_partial(in, tgt, r0,     tid);
    if (mm.y != 0) acc += (float)mm.y * row_partial(in, tgt, r0 + 1, tid);
    acc *= (1.0f / (float)DCOLS);

    // ---- block reduce ----
    #pragma unroll
    for (int off = 16; off > 0; off >>= 1)
        acc += __shfl_xor_sync(0xFFFFFFFFu, acc, off);

    __shared__ float warp_sums[BDIM / 32];
    const int wid = tid >> 5;
    const int lid = tid & 31;
    if (lid == 0) warp_sums[wid] = acc;
    __syncthreads();

    float block_sum = 0.0f;
    if (wid == 0) {
        float v = (lid < BDIM / 32) ? warp_sums[lid] : 0.0f;
        #pragma unroll
        for (int off = 4; off > 0; off >>= 1)
            v += __shfl_xor_sync(0xFFFFFFFFu, v, off);
        block_sum = v;
    }

    if (tid == 0)
        g_partials[bid] = block_sum;

    // ---- last-block-done detection ----
    __shared__ bool s_is_last;
    if (tid == 0) {
        __threadfence();
        unsigned int prev = atomicAdd(&g_done_count, 1u);
        s_is_last = (prev == NBLOCKS - 1);
    }
    __syncthreads();
    if (!s_is_last) return;

    if (tid == 0) g_done_count = 0;    // reset for next graph replay

    // ---- final deterministic reduce over 2048 partials ----
    float facc = 0.0f;
    #pragma unroll
    for (int it = 0; it < NBLOCKS / BDIM; ++it)
        facc += g_partials[it * BDIM + tid];

    #pragma unroll
    for (int off = 16; off > 0; off >>= 1)
        facc += __shfl_xor_sync(0xFFFFFFFFu, facc, off);

    __shared__ float fin_sums[BDIM / 32];
    if (lid == 0) fin_sums[wid] = facc;
    __syncthreads();

    if (wid == 0) {
        float v = (lid < BDIM / 32) ? fin_sums[lid] : 0.0f;
        #pragma unroll
        for (int off = 4; off > 0; off >>= 1)
            v += __shfl_xor_sync(0xFFFFFFFFu, v, off);
        if (lid == 0) out[0] = v;
    }
}

extern "C" void kernel_launch(void* const* d_in, const int* in_sizes, int n_in,
                              void* d_out, int out_size) {
    const float* inputs  = (const float*)d_in[0];
    const float* targets = (const float*)d_in[1];
    const int*   mask    = (const int*)d_in[2];
    float* out = (float*)d_out;

    mask_smoothl1_fused_kernel<<<NBLOCKS, BDIM>>>(inputs, targets, mask, out);
}